// round 17
// baseline (speedup 1.0000x reference)
#include <cuda_runtime.h>
#include <cuda_bf16.h>
#include <cstdint>

namespace {

constexpr int VJ = 25, TD = 300, CD = 256, NB = 32;
constexpr int NF   = VJ * TD;     // 7500 flattened (w,t)
constexpr int BM = 128, BN = 128, BK = 32;
constexpr int NCHUNK = CD / BK;   // 8
constexpr int THREADS = 256;
constexpr int NSTAGE = 3;

// per-stage smem: A fragments (16 KB) | B rows 32 x 132 floats (16896 B)
constexpr int BROW  = 132;                    // floats per B row (128 + 4 pad)
constexpr int OFF_A = 0;
constexpr int OFF_B = 16384;
constexpr int STAGE = OFF_B + BK * BROW * 4;  // 33280
constexpr int OFF_BAR = NSTAGE * STAGE;       // 99840: full[s]@+s*16, empty[s]@+s*16+8
constexpr int SMEM_DYN = OFF_BAR + 64;

// persistent scratch (allocation-free workaround)
__device__ float g_wt[CD * CD];   // W in m16n8k8 fragment order, tf32-rounded

__device__ __forceinline__ uint32_t smem_u32(const void* p) {
    uint32_t a;
    asm("{ .reg .u64 t; cvta.to.shared.u64 t, %1; cvt.u32.u64 %0, t; }" : "=r"(a) : "l"(p));
    return a;
}
__device__ __forceinline__ float tf32r(float v) {
    float r;
    asm("cvt.rna.tf32.f32 %0, %1;" : "=f"(r) : "f"(v));
    return r;
}
__device__ __forceinline__ void sts128(uint32_t addr, float4 v) {
    asm volatile("st.shared.v4.b32 [%0], {%1,%2,%3,%4};"
                 :: "r"(addr), "f"(v.x), "f"(v.y), "f"(v.z), "f"(v.w) : "memory");
}
__device__ __forceinline__ void lds128(uint32_t* r, uint32_t addr) {
    asm volatile("ld.shared.v4.b32 {%0,%1,%2,%3}, [%4];"
                 : "=r"(r[0]), "=r"(r[1]), "=r"(r[2]), "=r"(r[3]) : "r"(addr));
}
__device__ __forceinline__ uint32_t lds32(uint32_t addr) {
    uint32_t r;
    asm volatile("ld.shared.b32 %0, [%1];" : "=r"(r) : "r"(addr));
    return r;
}
__device__ __forceinline__ void mma_tf32(float* c, const uint32_t* a, uint32_t b0, uint32_t b1) {
    asm volatile(
        "mma.sync.aligned.m16n8k8.row.col.f32.tf32.tf32.f32 "
        "{%0,%1,%2,%3}, {%4,%5,%6,%7}, {%8,%9}, {%0,%1,%2,%3};"
        : "+f"(c[0]), "+f"(c[1]), "+f"(c[2]), "+f"(c[3])
        : "r"(a[0]), "r"(a[1]), "r"(a[2]), "r"(a[3]), "r"(b0), "r"(b1));
}
// ---- mbarrier primitives
__device__ __forceinline__ void mbar_init(uint32_t a, uint32_t cnt) {
    asm volatile("mbarrier.init.shared.b64 [%0], %1;" :: "r"(a), "r"(cnt) : "memory");
}
__device__ __forceinline__ void mbar_arrive(uint32_t a) {
    asm volatile("mbarrier.arrive.release.cta.shared::cta.b64 _, [%0];" :: "r"(a) : "memory");
}
__device__ __forceinline__ void mbar_wait(uint32_t mbar, uint32_t parity) {
    asm volatile(
        "{\n\t.reg .pred P1;\n\t"
        "WAIT_LOOP_%=:\n\t"
        "mbarrier.try_wait.parity.acquire.cta.shared::cta.b64 P1, [%0], %1;\n\t"
        "@P1 bra.uni WAIT_DONE_%=;\n\t"
        "bra.uni WAIT_LOOP_%=;\n\t"
        "WAIT_DONE_%=:\n\t}"
        :: "r"(mbar), "r"(parity) : "memory");
}

// ---- pre-pass: W -> tf32-rounded, m16n8k8 A-fragment order.
// blob index ((rblk*32 + cch)*32 + lane): 4 floats = a0..a3 of tile (rblk*16, cch*8)
__global__ void prep_w(const float* __restrict__ W) {
    const int i    = blockIdx.x * 256 + threadIdx.x;  // 0..16383
    const int lane = i & 31;
    const int cch  = (i >> 5) & 31;
    const int rblk = i >> 10;
    const int g  = lane >> 2, tg = lane & 3;
    const int R = rblk * 16, C = cch * 8;
    float4 v;
    v.x = tf32r(W[(R + g    ) * CD + C + tg    ]);
    v.y = tf32r(W[(R + g + 8) * CD + C + tg    ]);
    v.z = tf32r(W[(R + g    ) * CD + C + tg + 4]);
    v.w = tf32r(W[(R + g + 8) * CD + C + tg + 4]);
    reinterpret_cast<float4*>(g_wt)[i] = v;
}

// ---- fused GEMM: out[n] = W @ stencil(x[n]) (+bias); stencil computed in producer
__global__ __launch_bounds__(THREADS, 2)
void gemm_kernel(const float* __restrict__ x, const float* __restrict__ Aadj,
                 const float* __restrict__ bias, float* __restrict__ out)
{
    extern __shared__ char smem[];
    const uint32_t sb = smem_u32(smem);

    const int tid  = threadIdx.x;
    const int lane = tid & 31;
    const int wid  = tid >> 5;
    const int warp_m = wid & 1;    // 2 warps -> 64 rows each
    const int warp_n = wid >> 1;   // 4 warps -> 32 cols each

    const int nt0 = blockIdx.x * BN;
    const int m   = blockIdx.y;        // M-half
    const int n   = blockIdx.z;        // batch

    const uint32_t barb = sb + OFF_BAR;
    if (tid == 0) {
        #pragma unroll
        for (int s = 0; s < NSTAGE; ++s) {
            mbar_init(barb + s * 16,     THREADS);   // full[s]: 256 producer arrives
            mbar_init(barb + s * 16 + 8, THREADS);   // empty[s]: 256 consumer arrives
        }
    }
    __syncthreads();

    float acc[4][4][4];
    #pragma unroll
    for (int a = 0; a < 4; ++a)
        #pragma unroll
        for (int b = 0; b < 4; ++b)
            #pragma unroll
            for (int e = 0; e < 4; ++e) acc[a][b][e] = 0.0f;

    // produce(kcp): wait empty, LDG x + stencil + tf32 + STS (and A frag copy), arrive full
    auto produce = [&](int kcp) {
        const int s = kcp % NSTAGE;
        const int pass = kcp / NSTAGE;
        mbar_wait(barb + s * 16 + 8, (uint32_t)((pass & 1) ^ 1));  // empty[s]
        const uint32_t stb = sb + s * STAGE;
        const int c0 = kcp * BK;

        // ---- A tile: fragment-order blob, verbatim 16 KB copy
        {
            float4 av[4];
            const float4* wt4 = reinterpret_cast<const float4*>(g_wt);
            #pragma unroll
            for (int q = 0; q < 4; ++q) {
                const int idx = tid + q * 256;
                const int rl = idx >> 7, cl = (idx >> 5) & 3, l16 = idx & 31;
                av[q] = wt4[(size_t)(((8 * m + rl) * 32 + 4 * kcp + cl) * 32 + l16)];
            }
            #pragma unroll
            for (int q = 0; q < 4; ++q) {
                const int idx = tid + q * 256;
                const int rl = idx >> 7, cl = (idx >> 5) & 3, l16 = idx & 31;
                sts128(stb + OFF_A + (uint32_t)(rl * 2048 + cl * 512 + l16 * 16), av[q]);
            }
        }
        // ---- B tile: 3-tap stencil on x, tf32-rounded (two halves for reg pressure)
        #pragma unroll
        for (int h = 0; h < 2; ++h) {
            float4 vs[2], vp[2], vn[2];
            float as_[2], ap_[2], an_[2];
            uint32_t dsta[2];
            #pragma unroll
            for (int u = 0; u < 2; ++u) {
                const int idx = tid + (h * 2 + u) * 256;  // 0..1023
                const int k = idx >> 5, cc = idx & 31;
                dsta[u] = stb + OFF_B + (uint32_t)(k * (BROW * 4) + cc * 16);
                const int nf = nt0 + cc * 4;              // 16B chunk never crosses w boundary
                const bool valid = nf < NF;
                const int w = valid ? nf / TD : 0;
                const bool hp = valid && (w > 0);
                const bool hn = valid && (w < VJ - 1);
                const float* ps = x + ((size_t)(n * CD + c0 + k)) * NF + nf;
                vs[u] = valid ? *reinterpret_cast<const float4*>(ps)      : make_float4(0.f,0.f,0.f,0.f);
                vp[u] = hp    ? *reinterpret_cast<const float4*>(ps - TD) : make_float4(0.f,0.f,0.f,0.f);
                vn[u] = hn    ? *reinterpret_cast<const float4*>(ps + TD) : make_float4(0.f,0.f,0.f,0.f);
                as_[u] = valid ? Aadj[w * VJ + w]       : 0.0f;
                ap_[u] = hp    ? Aadj[(w - 1) * VJ + w] : 0.0f;
                an_[u] = hn    ? Aadj[(w + 1) * VJ + w] : 0.0f;
            }
            #pragma unroll
            for (int u = 0; u < 2; ++u) {
                float4 r;
                r.x = as_[u] * vs[u].x + ap_[u] * vp[u].x + an_[u] * vn[u].x;
                r.y = as_[u] * vs[u].y + ap_[u] * vp[u].y + an_[u] * vn[u].y;
                r.z = as_[u] * vs[u].z + ap_[u] * vp[u].z + an_[u] * vn[u].z;
                r.w = as_[u] * vs[u].w + ap_[u] * vp[u].w + an_[u] * vn[u].w;
                r.x = tf32r(r.x); r.y = tf32r(r.y); r.z = tf32r(r.z); r.w = tf32r(r.w);
                sts128(dsta[u], r);
            }
        }
        mbar_arrive(barb + s * 16);                                // full[s] (release)
    };

    produce(0);
    produce(1);

    const int g  = lane >> 2;
    const int tg = lane & 3;
    const uint32_t a_frag_off = OFF_A + (uint32_t)(warp_m * 4 * 2048 + lane * 16);
    // B word address component: (tg + koff)*BROW + n0 + g  (bank = 4tg+g+n0, conflict-free)
    const uint32_t b_off0 = OFF_B + (uint32_t)((tg * BROW + warp_n * 32 + g) * 4);

    auto lds_frag = [&](uint32_t stb, int ks, uint32_t a[4][4], uint32_t b[4][2]) {
        #pragma unroll
        for (int mt = 0; mt < 4; ++mt)
            lds128(a[mt], stb + a_frag_off + (uint32_t)(mt * 2048 + ks * 512));
        const uint32_t bbase = stb + b_off0 + (uint32_t)(ks * 8 * BROW * 4);
        #pragma unroll
        for (int nt = 0; nt < 4; ++nt) {
            b[nt][0] = lds32(bbase + (uint32_t)(nt * 8 * 4));
            b[nt][1] = lds32(bbase + (uint32_t)((4 * BROW + nt * 8) * 4));
        }
    };

    for (int kc = 0; kc < NCHUNK; ++kc) {
        if (kc + 2 < NCHUNK) produce(kc + 2);

        const int s = kc % NSTAGE;
        mbar_wait(barb + s * 16, (uint32_t)((kc / NSTAGE) & 1));   // full[s]

        const uint32_t stb = sb + s * STAGE;
        uint32_t a0[4][4], b0[4][2], a1[4][4], b1[4][2];
        lds_frag(stb, 0, a0, b0);
        #pragma unroll
        for (int ks = 0; ks < 4; ++ks) {
            uint32_t (*ac)[4] = (ks & 1) ? a1 : a0;
            uint32_t (*bc)[2] = (ks & 1) ? b1 : b0;
            if (ks < 3) {                    // prefetch next fragments during MMAs
                uint32_t (*an)[4] = (ks & 1) ? a0 : a1;
                uint32_t (*bn)[2] = (ks & 1) ? b0 : b1;
                lds_frag(stb, ks + 1, an, bn);
            }
            #pragma unroll
            for (int mt = 0; mt < 4; ++mt)
                #pragma unroll
                for (int nt = 0; nt < 4; ++nt)
                    mma_tf32(acc[mt][nt], ac[mt], bc[nt][0], bc[nt][1]);
        }
        mbar_arrive(barb + s * 16 + 8);                            // empty[s]
    }

    // ---- epilogue: c0=(g,2tg) c1=(g,2tg+1) c2=(g+8,2tg) c3=(g+8,2tg+1)
    #pragma unroll
    for (int mt = 0; mt < 4; ++mt) {
        const int o0 = m * BM + warp_m * 64 + mt * 16 + g;
        const float bv0 = bias[o0];
        const float bv1 = bias[o0 + 8];
        float* row0 = out + ((size_t)n * CD + o0    ) * NF;
        float* row1 = out + ((size_t)n * CD + o0 + 8) * NF;
        #pragma unroll
        for (int nt = 0; nt < 4; ++nt) {
            const int idx = nt0 + warp_n * 32 + nt * 8 + 2 * tg;   // even; NF even
            if (idx < NF) {
                float2 v0 = make_float2(acc[mt][nt][0] + bv0, acc[mt][nt][1] + bv0);
                float2 v1 = make_float2(acc[mt][nt][2] + bv1, acc[mt][nt][3] + bv1);
                *reinterpret_cast<float2*>(row0 + idx) = v0;
                *reinterpret_cast<float2*>(row1 + idx) = v1;
            }
        }
    }
}

} // namespace

extern "C" void kernel_launch(void* const* d_in, const int* in_sizes, int n_in,
                              void* d_out, int out_size) {
    const float* x    = (const float*)d_in[0];
    const float* A    = (const float*)d_in[1];
    const float* W    = (const float*)d_in[2];
    const float* b    = (const float*)d_in[3];
    float*       outp = (float*)d_out;

    prep_w<<<64, 256>>>(W);

    cudaFuncSetAttribute(gemm_kernel,
                         cudaFuncAttributeMaxDynamicSharedMemorySize, SMEM_DYN);
    dim3 grid((NF + BN - 1) / BN, 2, NB);   // 59 x 2 x 32 = 3776 CTAs
    gemm_kernel<<<grid, THREADS, SMEM_DYN>>>(x, A, b, outp);
}